// round 2
// baseline (speedup 1.0000x reference)
#include <cuda_runtime.h>

#define NB 64
#define NS 512
#define NTA 8
#define ND 768

// ---- scratch (no allocations allowed) ----
__device__ float g_mlen[NB], g_alen[NB];
__device__ float g_va[NB * ND], g_vs[NB * ND], g_ctx[NB * ND];
__device__ float g_scores[NB * NS];
__device__ float g_vns[NB * ND], g_vms[NB * ND];

// ---------------- lengths (ids are int32: JAX x64 is disabled) ----------------
__global__ void k_lens(const int* __restrict__ ids,
                       const int* __restrict__ tids) {
    int b = blockIdx.x;
    __shared__ int sm[128];
    int tid = threadIdx.x;
    int c = 0;
    for (int s = tid; s < NS; s += 128) c += (ids[b * NS + s] != 0);
    sm[tid] = c;
    __syncthreads();
    for (int o = 64; o > 0; o >>= 1) {
        if (tid < o) sm[tid] += sm[tid + o];
        __syncthreads();
    }
    if (tid == 0) {
        g_mlen[b] = fmaxf((float)sm[0], 1.0f);
        int a = 0;
        for (int t = 0; t < NTA; t++) a += (tids[b * NTA + t] != 0);
        g_alen[b] = fmaxf((float)a, 1.0f);
    }
}

// ---------------- means: v_s, v_a ----------------
__global__ void k_means(const float* __restrict__ mem,
                        const float* __restrict__ asp) {
    int b = blockIdx.y;
    int d = blockIdx.x * 128 + threadIdx.x;
    float acc = 0.f;
    const float* p = mem + ((size_t)b * NS) * ND + d;
#pragma unroll 4
    for (int s = 0; s < NS; s++) acc += p[(size_t)s * ND];
    g_vs[b * ND + d] = acc / g_mlen[b];
    float a = 0.f;
    const float* q = asp + ((size_t)b * NTA) * ND + d;
#pragma unroll
    for (int t = 0; t < NTA; t++) a += q[(size_t)t * ND];
    g_va[b * ND + d] = a / g_alen[b];
}

// ---------------- ctx = v_a @ W1_a + v_s @ W1_s + b1 ----------------
__global__ void k_ctx(const float* __restrict__ W1,
                      const float* __restrict__ b1) {
    __shared__ float sva[ND], svs[ND];
    int b = blockIdx.y;
    int d = blockIdx.x * 128 + threadIdx.x;
    for (int k = threadIdx.x; k < ND; k += 128) {
        sva[k] = g_va[b * ND + k];
        svs[k] = g_vs[b * ND + k];
    }
    __syncthreads();
    float acc = b1[d];
    const float* Wa = W1 + (size_t)ND * ND + d;       // rows D..2D-1
    const float* Ws = W1 + (size_t)2 * ND * ND + d;   // rows 2D..3D-1
#pragma unroll 4
    for (int k = 0; k < ND; k++) {
        acc = fmaf(sva[k], Wa[(size_t)k * ND], acc);
        acc = fmaf(svs[k], Ws[(size_t)k * ND], acc);
    }
    g_ctx[b * ND + d] = acc;
}

// ---------------- fused scores GEMM ----------------
// scores[b,s] = sum_d tanh( loc[b,s] * (mem[b,s,:] @ W1_m)[d] + ctx[b,d] ) * w2[d]
#define TM 64
#define TN 64
#define KC 16

__global__ __launch_bounds__(256) void k_scores(const float* __restrict__ mem,
                                                const float* __restrict__ W1,
                                                const float* __restrict__ w2) {
    __shared__ float As[KC][TM];
    __shared__ float Bs[KC][TN];
    __shared__ float sred[TM][16];

    int b = blockIdx.y;
    int s0 = blockIdx.x * TM;
    int tid = threadIdx.x;
    int tx = tid & 15;   // 0..15 -> 4 cols each
    int ty = tid >> 4;   // 0..15 -> 4 rows each

    float mlen = g_mlen[b];
    float loc[4];
#pragma unroll
    for (int i = 0; i < 4; i++) {
        float s = (float)(s0 + ty * 4 + i);
        loc[i] = (s < mlen) ? (1.0f - s / mlen) : 1.0f;
    }

    // A (memory) staging indices: thread loads float4 along K, stores transposed
    int am = tid >> 2;           // row 0..63
    int ak = (tid & 3) * 4;      // k offset 0,4,8,12
    const float* Abase = mem + ((size_t)b * NS + s0 + am) * ND + ak;
    // B (W1_m) staging indices
    int bk = tid >> 4;           // 0..15
    int bn = (tid & 15) * 4;     // 0..60

    float spart[4] = {0.f, 0.f, 0.f, 0.f};

    for (int n0 = 0; n0 < ND; n0 += TN) {
        float acc[4][4];
#pragma unroll
        for (int i = 0; i < 4; i++)
#pragma unroll
            for (int j = 0; j < 4; j++) acc[i][j] = 0.f;

        const float* Bbase = W1 + (size_t)bk * ND + n0 + bn;

        for (int k0 = 0; k0 < ND; k0 += KC) {
            float4 av = *(const float4*)(Abase + k0);
            float4 bv = *(const float4*)(Bbase + (size_t)k0 * ND);
            As[ak + 0][am] = av.x;
            As[ak + 1][am] = av.y;
            As[ak + 2][am] = av.z;
            As[ak + 3][am] = av.w;
            *(float4*)&Bs[bk][bn] = bv;
            __syncthreads();
#pragma unroll
            for (int kk = 0; kk < KC; kk++) {
                float4 a4 = *(const float4*)&As[kk][ty * 4];
                float4 b4 = *(const float4*)&Bs[kk][tx * 4];
                float ar[4] = {a4.x, a4.y, a4.z, a4.w};
                float br[4] = {b4.x, b4.y, b4.z, b4.w};
#pragma unroll
                for (int i = 0; i < 4; i++)
#pragma unroll
                    for (int j = 0; j < 4; j++)
                        acc[i][j] = fmaf(ar[i], br[j], acc[i][j]);
            }
            __syncthreads();
        }

        // epilogue: tanh + dot with w2 over this N tile
        float4 c4 = *(const float4*)(g_ctx + b * ND + n0 + tx * 4);
        float4 w4 = *(const float4*)(w2 + n0 + tx * 4);
        float cv[4] = {c4.x, c4.y, c4.z, c4.w};
        float wv[4] = {w4.x, w4.y, w4.z, w4.w};
#pragma unroll
        for (int i = 0; i < 4; i++) {
#pragma unroll
            for (int j = 0; j < 4; j++) {
                float u = fmaf(loc[i], acc[i][j], cv[j]);
                spart[i] = fmaf(tanhf(u), wv[j], spart[i]);
            }
        }
    }

    // deterministic reduction across the 16 column-threads of each row
#pragma unroll
    for (int i = 0; i < 4; i++) sred[ty * 4 + i][tx] = spart[i];
    __syncthreads();
    if (tid < TM) {
        float s = 0.f;
#pragma unroll
        for (int j = 0; j < 16; j++) s += sred[tid][j];
        g_scores[b * NS + s0 + tid] = s;
    }
}

// ---------------- softmax + v_ts + v_ns ----------------
__global__ __launch_bounds__(256) void k_soft_vts(const float* __restrict__ mem) {
    int b = blockIdx.x;
    __shared__ float sw[NS];
    __shared__ float red[256];
    int tid = threadIdx.x;
    float mlen = g_mlen[b];

    float v0 = g_scores[b * NS + tid];
    float v1 = g_scores[b * NS + 256 + tid];

    red[tid] = fmaxf(v0, v1);
    __syncthreads();
    for (int o = 128; o > 0; o >>= 1) {
        if (tid < o) red[tid] = fmaxf(red[tid], red[tid + o]);
        __syncthreads();
    }
    float m = red[0];
    __syncthreads();

    float e0 = expf(v0 - m), e1 = expf(v1 - m);
    red[tid] = e0 + e1;
    __syncthreads();
    for (int o = 128; o > 0; o >>= 1) {
        if (tid < o) red[tid] += red[tid + o];
        __syncthreads();
    }
    float inv = 1.0f / red[0];
    __syncthreads();

    float sA = (float)tid, sB = (float)(tid + 256);
    float lA = (sA < mlen) ? (1.0f - sA / mlen) : 1.0f;
    float lB = (sB < mlen) ? (1.0f - sB / mlen) : 1.0f;
    sw[tid] = e0 * inv * lA;
    sw[tid + 256] = e1 * inv * lB;
    __syncthreads();

    for (int d = tid; d < ND; d += 256) {
        float acc = 0.f;
        const float* p = mem + ((size_t)b * NS) * ND + d;
#pragma unroll 4
        for (int s = 0; s < NS; s++) acc = fmaf(sw[s], p[(size_t)s * ND], acc);
        g_vns[b * ND + d] = acc + g_vs[b * ND + d];
    }
}

// ---------------- v_ms = tanh(v_ns @ Wm + bm) ----------------
__global__ void k_vms(const float* __restrict__ Wm,
                      const float* __restrict__ bm) {
    __shared__ float sv[ND];
    int b = blockIdx.y;
    int d = blockIdx.x * 128 + threadIdx.x;
    for (int k = threadIdx.x; k < ND; k += 128) sv[k] = g_vns[b * ND + k];
    __syncthreads();
    float acc = bm[d];
#pragma unroll 4
    for (int k = 0; k < ND; k++) acc = fmaf(sv[k], Wm[(size_t)k * ND + d], acc);
    g_vms[b * ND + d] = tanhf(acc);
}

// ---------------- logits ----------------
__global__ void k_logits(const float* __restrict__ Wd,
                         const float* __restrict__ bd,
                         float* __restrict__ out) {
    int t = threadIdx.x;
    if (t >= NB * 3) return;
    int b = t / 3, j = t % 3;
    float acc = bd[j];
    const float* v = g_vms + b * ND;
#pragma unroll 4
    for (int d = 0; d < ND; d++) acc = fmaf(v[d], Wd[d * 3 + j], acc);
    out[b * 3 + j] = acc;
}

// ---------------- launch ----------------
extern "C" void kernel_launch(void* const* d_in, const int* in_sizes, int n_in,
                              void* d_out, int out_size) {
    (void)in_sizes; (void)n_in; (void)out_size;
    const float* mem   = (const float*)d_in[0];
    const float* asp   = (const float*)d_in[1];
    const int* ids     = (const int*)d_in[2];
    const int* tids    = (const int*)d_in[3];
    const float* W1 = (const float*)d_in[4];
    const float* b1 = (const float*)d_in[5];
    const float* w2 = (const float*)d_in[6];
    const float* Wm = (const float*)d_in[7];
    const float* bm = (const float*)d_in[8];
    const float* Wd = (const float*)d_in[9];
    const float* bd = (const float*)d_in[10];
    float* out = (float*)d_out;

    k_lens<<<NB, 128>>>(ids, tids);
    k_means<<<dim3(ND / 128, NB), 128>>>(mem, asp);
    k_ctx<<<dim3(ND / 128, NB), 128>>>(W1, b1);
    k_scores<<<dim3(NS / TM, NB), 256>>>(mem, W1, w2);
    k_soft_vts<<<NB, 256>>>(mem);
    k_vms<<<dim3(ND / 128, NB), 128>>>(Wm, bm);
    k_logits<<<1, 256>>>(Wd, bd, out);
}

// round 4
// speedup vs baseline: 2.6140x; 2.6140x over previous
#include <cuda_runtime.h>
#include <cuda_bf16.h>
#include <cuda_fp16.h>
#include <cstdint>

#define NB 64
#define NS 512
#define NTA 8
#define ND 768

// ------------------------------------------------------------------
// scratch (static __device__; no allocations allowed)
// ------------------------------------------------------------------
__device__ float g_mlen[NB], g_alen[NB];
__device__ float g_va[NB * ND], g_vs[NB * ND], g_ctx[NB * ND];
__device__ float g_scores[NB * NS];
__device__ float g_vns[NB * ND], g_vms[NB * ND];

// bf16 hi/lo splits
__device__ __nv_bfloat16 g_Ahi[(size_t)NB * NS * ND];
__device__ __nv_bfloat16 g_Alo[(size_t)NB * NS * ND];
__device__ __nv_bfloat16 g_Bhi[(size_t)ND * ND];   // [n][k] = W1_m[k][n]
__device__ __nv_bfloat16 g_Blo[(size_t)ND * ND];

// ------------------------------------------------------------------
// PTX helpers (baseline ISA only; no sm_103a-gated features)
// ------------------------------------------------------------------
__device__ __forceinline__ uint32_t smem_u32(const void* p) {
    uint32_t a;
    asm("{ .reg .u64 t; cvta.to.shared.u64 t, %1; cvt.u32.u64 %0, t; }" : "=r"(a) : "l"(p));
    return a;
}
__device__ __forceinline__ void cp16(uint32_t dst, const void* src) {
    asm volatile("cp.async.cg.shared.global [%0], [%1], 16;" :: "r"(dst), "l"(src));
}
#define CP_COMMIT() asm volatile("cp.async.commit_group;" ::: "memory")
#define CP_WAIT1()  asm volatile("cp.async.wait_group 1;" ::: "memory")
#define CP_WAIT0()  asm volatile("cp.async.wait_group 0;" ::: "memory")

__device__ __forceinline__ void ldsm4(uint32_t& r0, uint32_t& r1, uint32_t& r2, uint32_t& r3,
                                      uint32_t addr) {
    asm volatile("ldmatrix.sync.aligned.m8n8.x4.shared.b16 {%0,%1,%2,%3}, [%4];"
                 : "=r"(r0), "=r"(r1), "=r"(r2), "=r"(r3) : "r"(addr));
}
__device__ __forceinline__ void mma16816(float* c, uint32_t a0, uint32_t a1, uint32_t a2,
                                         uint32_t a3, uint32_t b0, uint32_t b1) {
    asm volatile(
        "mma.sync.aligned.m16n8k16.row.col.f32.bf16.bf16.f32 "
        "{%0,%1,%2,%3}, {%4,%5,%6,%7}, {%8,%9}, {%0,%1,%2,%3};"
        : "+f"(c[0]), "+f"(c[1]), "+f"(c[2]), "+f"(c[3])
        : "r"(a0), "r"(a1), "r"(a2), "r"(a3), "r"(b0), "r"(b1));
}
__device__ __forceinline__ uint32_t tanh2_f16(uint32_t x) {
    uint32_t y;
    asm("tanh.approx.f16x2 %0, %1;" : "=r"(y) : "r"(x));
    return y;
}

// ------------------------------------------------------------------
// lengths (ids are int32)
// ------------------------------------------------------------------
__global__ void k_lens(const int* __restrict__ ids, const int* __restrict__ tids) {
    int b = blockIdx.x;
    __shared__ int sm[128];
    int tid = threadIdx.x;
    int c = 0;
    for (int s = tid; s < NS; s += 128) c += (ids[b * NS + s] != 0);
    sm[tid] = c;
    __syncthreads();
    for (int o = 64; o > 0; o >>= 1) {
        if (tid < o) sm[tid] += sm[tid + o];
        __syncthreads();
    }
    if (tid == 0) {
        g_mlen[b] = fmaxf((float)sm[0], 1.0f);
        int a = 0;
        for (int t = 0; t < NTA; t++) a += (tids[b * NTA + t] != 0);
        g_alen[b] = fmaxf((float)a, 1.0f);
    }
}

// ------------------------------------------------------------------
// split memory -> bf16 hi/lo
// ------------------------------------------------------------------
__global__ __launch_bounds__(256) void k_prep_a(const float* __restrict__ mem) {
    size_t i = ((size_t)blockIdx.x * 256 + threadIdx.x) * 4;
    float4 v = *(const float4*)(mem + i);
    float vv[4] = {v.x, v.y, v.z, v.w};
    __nv_bfloat16 h[4], l[4];
#pragma unroll
    for (int j = 0; j < 4; j++) {
        h[j] = __float2bfloat16(vv[j]);
        l[j] = __float2bfloat16(vv[j] - __bfloat162float(h[j]));
    }
    *(uint2*)(g_Ahi + i) = *(uint2*)h;
    *(uint2*)(g_Alo + i) = *(uint2*)l;
}

// transpose + split W1_m: g_B[n][k] = W1[k][n]
__global__ void k_prep_b(const float* __restrict__ W1) {
    __shared__ float t[32][33];
    int k0 = blockIdx.x * 32, n0 = blockIdx.y * 32;
    int tx = threadIdx.x, ty = threadIdx.y;
    for (int i = ty; i < 32; i += 8)
        t[i][tx] = W1[(size_t)(k0 + i) * ND + n0 + tx];
    __syncthreads();
    for (int i = ty; i < 32; i += 8) {
        float v = t[tx][i];
        __nv_bfloat16 h = __float2bfloat16(v);
        __nv_bfloat16 l = __float2bfloat16(v - __bfloat162float(h));
        g_Bhi[(size_t)(n0 + i) * ND + k0 + tx] = h;
        g_Blo[(size_t)(n0 + i) * ND + k0 + tx] = l;
    }
}

// ------------------------------------------------------------------
// means: v_s, v_a  (512 threads: 4-way s-split)
// ------------------------------------------------------------------
__global__ __launch_bounds__(512) void k_means(const float* __restrict__ mem,
                                               const float* __restrict__ asp) {
    __shared__ float sp[4][128];
    int b = blockIdx.y;
    int tid = threadIdx.x;
    int d = blockIdx.x * 128 + (tid & 127);
    int q = tid >> 7;
    float acc = 0.f;
    const float* p = mem + ((size_t)b * NS + q * 128) * ND + d;
#pragma unroll 8
    for (int s = 0; s < 128; s++) acc += p[(size_t)s * ND];
    sp[q][tid & 127] = acc;
    __syncthreads();
    if (q == 0) {
        float tot = sp[0][tid] + sp[1][tid] + sp[2][tid] + sp[3][tid];
        g_vs[b * ND + d] = tot / g_mlen[b];
        float a = 0.f;
        const float* ap = asp + ((size_t)b * NTA) * ND + d;
#pragma unroll
        for (int t = 0; t < NTA; t++) a += ap[(size_t)t * ND];
        g_va[b * ND + d] = a / g_alen[b];
    }
}

// ------------------------------------------------------------------
// ctx = v_a @ W1_a + v_s @ W1_s + b1  (512 threads: 4-way split)
// ------------------------------------------------------------------
__global__ __launch_bounds__(512) void k_ctx(const float* __restrict__ W1,
                                             const float* __restrict__ b1) {
    __shared__ float sp[4][128];
    int b = blockIdx.y;
    int tid = threadIdx.x;
    int d = blockIdx.x * 128 + (tid & 127);
    int q = tid >> 7;                     // 0,1 -> Wa halves; 2,3 -> Ws halves
    const float* W = W1 + (size_t)(1 + (q >> 1)) * ND * ND + d;
    const float* vv = ((q >> 1) ? g_vs : g_va) + b * ND;
    int k0 = (q & 1) * 384;
    float acc = 0.f;
#pragma unroll 8
    for (int k = 0; k < 384; k++)
        acc = fmaf(vv[k0 + k], W[(size_t)(k0 + k) * ND], acc);
    sp[q][tid & 127] = acc;
    __syncthreads();
    if (q == 0)
        g_ctx[b * ND + d] = sp[0][tid] + sp[1][tid] + sp[2][tid] + sp[3][tid] + b1[d];
}

// ------------------------------------------------------------------
// fused scores: mma.sync bf16 3xMMA GEMM + tanh/w2 epilogue
//   D[m,n] = sum_k mem[m,k]*W1_m[k,n]  (CTA: M=128 rows, N=64 chunk, K=768)
//   scores[m] = sum_n tanh(loc[m]*D[m,n] + ctx[n]) * w2[n]
// ------------------------------------------------------------------
#define MT 128
#define NTILE 64
#define KC 32
#define NCHUNKS (ND / NTILE)   // 12
#define KSTEPS (ND / KC)       // 24
#define APAD 80                // padded row stride (bytes): conflict-free ldmatrix

#define OFF_AH 0
#define OFF_AL 10240
#define OFF_BH 20480
#define OFF_BL 25600
#define BUFSZ  30720
#define OFF_CTX (2 * BUFSZ)          // 61440
#define OFF_W2  (OFF_CTX + 3072)     // 64512
#define OFF_RED (OFF_W2 + 3072)      // 67584
#define SMEMSZ  (OFF_RED + 1024)     // 68608

struct ScoreCtx {
    const __nv_bfloat16* gAh;
    const __nv_bfloat16* gAl;
    uint32_t sbase;
};

__device__ __forceinline__ void stage_tiles(const ScoreCtx& sc, int nbase, int k0, int buf) {
    int tid = threadIdx.x;
    uint32_t sb = sc.sbase + buf * BUFSZ;
#pragma unroll
    for (int t = 0; t < 2; t++) {
        int i = tid + t * 256;
        int r = i >> 2, c = i & 3;
        const __nv_bfloat16* sh = sc.gAh + (size_t)r * ND + k0 + c * 8;
        const __nv_bfloat16* sl = sc.gAl + (size_t)r * ND + k0 + c * 8;
        uint32_t d = sb + r * APAD + c * 16;
        cp16(d + OFF_AH, sh);
        cp16(d + OFF_AL, sl);
    }
    {
        int r = tid >> 2, c = tid & 3;
        const __nv_bfloat16* sh = g_Bhi + (size_t)(nbase + r) * ND + k0 + c * 8;
        const __nv_bfloat16* sl = g_Blo + (size_t)(nbase + r) * ND + k0 + c * 8;
        uint32_t d = sb + r * APAD + c * 16;
        cp16(d + OFF_BH, sh);
        cp16(d + OFF_BL, sl);
    }
}

__global__ void __launch_bounds__(256, 2) k_scores(const float* __restrict__ w2) {
    extern __shared__ char smem[];
    const int tid = threadIdx.x;
    const int b = blockIdx.y;
    const int s0 = blockIdx.x * MT;
    const int lane = tid & 31, wid = tid >> 5;
    const int warp_m = wid & 3, warp_n = wid >> 2;

    float* sctx = (float*)(smem + OFF_CTX);
    float* sw2p = (float*)(smem + OFF_W2);
    for (int i = tid; i < ND; i += 256) {
        sctx[i] = g_ctx[b * ND + i];
        sw2p[i] = w2[i];
    }

    ScoreCtx sc;
    sc.gAh = g_Ahi + ((size_t)b * NS + s0) * ND;
    sc.gAl = g_Alo + ((size_t)b * NS + s0) * ND;
    sc.sbase = smem_u32(smem);

    const float mlen = g_mlen[b];
    float loc[2][2], rowsum[2][2];
#pragma unroll
    for (int mt = 0; mt < 2; mt++)
#pragma unroll
        for (int h = 0; h < 2; h++) {
            float srow = (float)(s0 + warp_m * 32 + mt * 16 + h * 8 + (lane >> 2));
            loc[mt][h] = (srow < mlen) ? (1.0f - srow / mlen) : 1.0f;
            rowsum[mt][h] = 0.f;
        }

    // ldmatrix lane geometry
    const int a_row = warp_m * 32 + (lane & 7) + ((lane >> 3) & 1) * 8;  // + mt*16
    const int a_halfoff = (lane >> 4) * 16;
    const int b_row = warp_n * 32 + (lane & 7) + (lane >> 4) * 8;        // + ntt*16
    const int b_halfoff = ((lane >> 3) & 1) * 16;

    __syncthreads();  // sctx/sw2 ready

    // prologue: stage chunk0 / ks0 into buf0
    stage_tiles(sc, 0, 0, 0);
    CP_COMMIT();

    for (int chunk = 0; chunk < NCHUNKS; chunk++) {
        const int nbase = chunk * NTILE;
        float acc[2][4][4];
#pragma unroll
        for (int mt = 0; mt < 2; mt++)
#pragma unroll
            for (int nt = 0; nt < 4; nt++)
#pragma unroll
                for (int j = 0; j < 4; j++) acc[mt][nt][j] = 0.f;

        for (int ks = 0; ks < KSTEPS; ks++) {
            const int buf = ks & 1;
            if (ks + 1 < KSTEPS) {
                stage_tiles(sc, nbase, (ks + 1) * KC, buf ^ 1);
                CP_COMMIT();
                CP_WAIT1();
            } else {
                CP_WAIT0();
            }
            __syncthreads();

            const uint32_t sb = sc.sbase + buf * BUFSZ;
#pragma unroll
            for (int kk = 0; kk < 2; kk++) {
                const int kb = kk * 32;
                uint32_t ar[2][4], br[2][4];
                // A hi
#pragma unroll
                for (int mt = 0; mt < 2; mt++)
                    ldsm4(ar[mt][0], ar[mt][1], ar[mt][2], ar[mt][3],
                          sb + OFF_AH + (a_row + mt * 16) * APAD + kb + a_halfoff);
                // B hi
#pragma unroll
                for (int nt2 = 0; nt2 < 2; nt2++)
                    ldsm4(br[nt2][0], br[nt2][1], br[nt2][2], br[nt2][3],
                          sb + OFF_BH + (b_row + nt2 * 16) * APAD + kb + b_halfoff);
                // Ah * Bh
#pragma unroll
                for (int mt = 0; mt < 2; mt++)
#pragma unroll
                    for (int nt2 = 0; nt2 < 2; nt2++)
#pragma unroll
                        for (int s = 0; s < 2; s++)
                            mma16816(acc[mt][nt2 * 2 + s], ar[mt][0], ar[mt][1], ar[mt][2],
                                     ar[mt][3], br[nt2][2 * s], br[nt2][2 * s + 1]);
                // A lo  -> Al * Bh
#pragma unroll
                for (int mt = 0; mt < 2; mt++)
                    ldsm4(ar[mt][0], ar[mt][1], ar[mt][2], ar[mt][3],
                          sb + OFF_AL + (a_row + mt * 16) * APAD + kb + a_halfoff);
#pragma unroll
                for (int mt = 0; mt < 2; mt++)
#pragma unroll
                    for (int nt2 = 0; nt2 < 2; nt2++)
#pragma unroll
                        for (int s = 0; s < 2; s++)
                            mma16816(acc[mt][nt2 * 2 + s], ar[mt][0], ar[mt][1], ar[mt][2],
                                     ar[mt][3], br[nt2][2 * s], br[nt2][2 * s + 1]);
                // reload A hi, B lo -> Ah * Bl
#pragma unroll
                for (int mt = 0; mt < 2; mt++)
                    ldsm4(ar[mt][0], ar[mt][1], ar[mt][2], ar[mt][3],
                          sb + OFF_AH + (a_row + mt * 16) * APAD + kb + a_halfoff);
#pragma unroll
                for (int nt2 = 0; nt2 < 2; nt2++)
                    ldsm4(br[nt2][0], br[nt2][1], br[nt2][2], br[nt2][3],
                          sb + OFF_BL + (b_row + nt2 * 16) * APAD + kb + b_halfoff);
#pragma unroll
                for (int mt = 0; mt < 2; mt++)
#pragma unroll
                    for (int nt2 = 0; nt2 < 2; nt2++)
#pragma unroll
                        for (int s = 0; s < 2; s++)
                            mma16816(acc[mt][nt2 * 2 + s], ar[mt][0], ar[mt][1], ar[mt][2],
                                     ar[mt][3], br[nt2][2 * s], br[nt2][2 * s + 1]);
            }
            __syncthreads();
        }

        // prefetch next chunk's first stage (overlaps with epilogue MUFU work)
        if (chunk + 1 < NCHUNKS) {
            stage_tiles(sc, nbase + NTILE, 0, 0);
            CP_COMMIT();
        }

        // epilogue: tanh (f16x2) + dot with w2
#pragma unroll
        for (int mt = 0; mt < 2; mt++) {
#pragma unroll
            for (int nt = 0; nt < 4; nt++) {
                const int c0 = nbase + warp_n * 32 + nt * 8 + (lane & 3) * 2;
                const float2 cx = *(const float2*)&sctx[c0];
                const float2 wv = *(const float2*)&sw2p[c0];
                {
                    float u0 = fmaf(loc[mt][0], acc[mt][nt][0], cx.x);
                    float u1 = fmaf(loc[mt][0], acc[mt][nt][1], cx.y);
                    __half2 hp = __floats2half2_rn(u0, u1);
                    uint32_t th = tanh2_f16(*(uint32_t*)&hp);
                    float2 tf = __half22float2(*(__half2*)&th);
                    rowsum[mt][0] = fmaf(tf.x, wv.x, fmaf(tf.y, wv.y, rowsum[mt][0]));
                }
                {
                    float u2 = fmaf(loc[mt][1], acc[mt][nt][2], cx.x);
                    float u3 = fmaf(loc[mt][1], acc[mt][nt][3], cx.y);
                    __half2 hp = __floats2half2_rn(u2, u3);
                    uint32_t th = tanh2_f16(*(uint32_t*)&hp);
                    float2 tf = __half22float2(*(__half2*)&th);
                    rowsum[mt][1] = fmaf(tf.x, wv.x, fmaf(tf.y, wv.y, rowsum[mt][1]));
                }
            }
        }
    }

    // reduce across the 4 lanes of each quad, then across warp_n via smem
    float* red = (float*)(smem + OFF_RED);
#pragma unroll
    for (int mt = 0; mt < 2; mt++)
#pragma unroll
        for (int h = 0; h < 2; h++) {
            float v = rowsum[mt][h];
            v += __shfl_xor_sync(0xffffffffu, v, 1);
            v += __shfl_xor_sync(0xffffffffu, v, 2);
            if ((lane & 3) == 0) {
                int lrow = warp_m * 32 + mt * 16 + h * 8 + (lane >> 2);
                red[lrow * 2 + warp_n] = v;
            }
        }
    __syncthreads();
    if (tid < MT)
        g_scores[b * NS + s0 + tid] = red[tid * 2] + red[tid * 2 + 1];
}

// ------------------------------------------------------------------
// softmax + v_ts + v_ns  (512 threads)
// ------------------------------------------------------------------
__global__ __launch_bounds__(512) void k_soft_vts(const float* __restrict__ mem) {
    int b = blockIdx.x;
    int tid = threadIdx.x;
    __shared__ float sw[NS];
    __shared__ float red[512];
    __shared__ float sp[2][256];
    float mlen = g_mlen[b];

    float v = g_scores[b * NS + tid];
    red[tid] = v;
    __syncthreads();
    for (int o = 256; o > 0; o >>= 1) {
        if (tid < o) red[tid] = fmaxf(red[tid], red[tid + o]);
        __syncthreads();
    }
    float m = red[0];
    __syncthreads();
    float e = expf(v - m);
    red[tid] = e;
    __syncthreads();
    for (int o = 256; o > 0; o >>= 1) {
        if (tid < o) red[tid] += red[tid + o];
        __syncthreads();
    }
    float inv = 1.0f / red[0];
    __syncthreads();
    float s = (float)tid;
    float l = (s < mlen) ? (1.0f - s / mlen) : 1.0f;
    sw[tid] = e * inv * l;
    __syncthreads();

    int dq = tid >> 8;
    int dd = tid & 255;
    for (int dc = 0; dc < 3; dc++) {
        int d = dc * 256 + dd;
        const float* p = mem + ((size_t)b * NS + dq * 256) * ND + d;
        float acc = 0.f;
#pragma unroll 8
        for (int s2 = 0; s2 < 256; s2++)
            acc = fmaf(sw[dq * 256 + s2], p[(size_t)s2 * ND], acc);
        sp[dq][dd] = acc;
        __syncthreads();
        if (dq == 0)
            g_vns[b * ND + d] = sp[0][dd] + sp[1][dd] + g_vs[b * ND + d];
        __syncthreads();
    }
}

// ------------------------------------------------------------------
// v_ms = tanh(v_ns @ Wm + bm)  (512 threads: 4-way k-split)
// ------------------------------------------------------------------
__global__ __launch_bounds__(512) void k_vms(const float* __restrict__ Wm,
                                             const float* __restrict__ bm) {
    __shared__ float sp[4][128];
    int b = blockIdx.y;
    int tid = threadIdx.x;
    int d = blockIdx.x * 128 + (tid & 127);
    int q = tid >> 7;
    const float* vv = g_vns + b * ND;
    int k0 = q * 192;
    float acc = 0.f;
#pragma unroll 8
    for (int k = 0; k < 192; k++)
        acc = fmaf(vv[k0 + k], Wm[(size_t)(k0 + k) * ND + d], acc);
    sp[q][tid & 127] = acc;
    __syncthreads();
    if (q == 0)
        g_vms[b * ND + d] = tanhf(sp[0][tid] + sp[1][tid] + sp[2][tid] + sp[3][tid] + bm[d]);
}

// ------------------------------------------------------------------
// logits
// ------------------------------------------------------------------
__global__ void k_logits(const float* __restrict__ Wd,
                         const float* __restrict__ bd,
                         float* __restrict__ out) {
    int t = threadIdx.x;
    if (t >= NB * 3) return;
    int b = t / 3, j = t % 3;
    float acc = bd[j];
    const float* v = g_vms + b * ND;
#pragma unroll 4
    for (int d = 0; d < ND; d++) acc = fmaf(v[d], Wd[d * 3 + j], acc);
    out[b * 3 + j] = acc;
}

// ------------------------------------------------------------------
// launch
// ------------------------------------------------------------------
extern "C" void kernel_launch(void* const* d_in, const int* in_sizes, int n_in,
                              void* d_out, int out_size) {
    (void)in_sizes; (void)n_in; (void)out_size;
    const float* mem  = (const float*)d_in[0];
    const float* asp  = (const float*)d_in[1];
    const int* ids    = (const int*)d_in[2];
    const int* tids   = (const int*)d_in[3];
    const float* W1 = (const float*)d_in[4];
    const float* b1 = (const float*)d_in[5];
    const float* w2 = (const float*)d_in[6];
    const float* Wm = (const float*)d_in[7];
    const float* bm = (const float*)d_in[8];
    const float* Wd = (const float*)d_in[9];
    const float* bd = (const float*)d_in[10];
    float* out = (float*)d_out;

    cudaFuncSetAttribute(k_scores, cudaFuncAttributeMaxDynamicSharedMemorySize, SMEMSZ);

    k_lens<<<NB, 128>>>(ids, tids);
    k_prep_a<<<(int)(((size_t)NB * NS * ND) / (256 * 4)), 256>>>(mem);
    k_prep_b<<<dim3(ND / 32, ND / 32), dim3(32, 8)>>>(W1);
    k_means<<<dim3(ND / 128, NB), 512>>>(mem, asp);
    k_ctx<<<dim3(ND / 128, NB), 512>>>(W1, b1);
    k_scores<<<dim3(NS / MT, NB), 256, SMEMSZ>>>(w2);
    k_soft_vts<<<NB, 512>>>(mem);
    k_vms<<<dim3(ND / 128, NB), 512>>>(Wm, bm);
    k_logits<<<1, 256>>>(Wd, bd, out);
}

// round 5
// speedup vs baseline: 2.8883x; 1.1049x over previous
#include <cuda_runtime.h>
#include <cuda_bf16.h>
#include <cuda_fp16.h>
#include <cstdint>

#define NB 64
#define NS 512
#define NTA 8
#define ND 768

// ------------------------------------------------------------------
// scratch (static __device__; no allocations allowed)
// ------------------------------------------------------------------
__device__ float g_mlen[NB], g_alen[NB];
__device__ float g_va[NB * ND], g_vs[NB * ND], g_ctx[NB * ND];
__device__ float g_scores[NB * NS];
__device__ float g_vns[NB * ND], g_vms[NB * ND];

// bf16 hi/lo splits
__device__ __nv_bfloat16 g_Ahi[(size_t)NB * NS * ND];
__device__ __nv_bfloat16 g_Alo[(size_t)NB * NS * ND];
__device__ __nv_bfloat16 g_Bhi[(size_t)ND * ND];   // [n][k] = W1_m[k][n]
__device__ __nv_bfloat16 g_Blo[(size_t)ND * ND];

// ------------------------------------------------------------------
// PTX helpers (baseline ISA only; no sm_103a-gated features)
// ------------------------------------------------------------------
__device__ __forceinline__ uint32_t smem_u32(const void* p) {
    uint32_t a;
    asm("{ .reg .u64 t; cvta.to.shared.u64 t, %1; cvt.u32.u64 %0, t; }" : "=r"(a) : "l"(p));
    return a;
}
__device__ __forceinline__ void cp16(uint32_t dst, const void* src) {
    asm volatile("cp.async.cg.shared.global [%0], [%1], 16;" :: "r"(dst), "l"(src));
}
#define CP_COMMIT() asm volatile("cp.async.commit_group;" ::: "memory")
#define CP_WAIT1()  asm volatile("cp.async.wait_group 1;" ::: "memory")
#define CP_WAIT0()  asm volatile("cp.async.wait_group 0;" ::: "memory")

__device__ __forceinline__ void ldsm4(uint32_t& r0, uint32_t& r1, uint32_t& r2, uint32_t& r3,
                                      uint32_t addr) {
    asm volatile("ldmatrix.sync.aligned.m8n8.x4.shared.b16 {%0,%1,%2,%3}, [%4];"
                 : "=r"(r0), "=r"(r1), "=r"(r2), "=r"(r3) : "r"(addr));
}
__device__ __forceinline__ void mma16816(float* c, uint32_t a0, uint32_t a1, uint32_t a2,
                                         uint32_t a3, uint32_t b0, uint32_t b1) {
    asm volatile(
        "mma.sync.aligned.m16n8k16.row.col.f32.bf16.bf16.f32 "
        "{%0,%1,%2,%3}, {%4,%5,%6,%7}, {%8,%9}, {%0,%1,%2,%3};"
        : "+f"(c[0]), "+f"(c[1]), "+f"(c[2]), "+f"(c[3])
        : "r"(a0), "r"(a1), "r"(a2), "r"(a3), "r"(b0), "r"(b1));
}
__device__ __forceinline__ uint32_t tanh2_f16(uint32_t x) {
    uint32_t y;
    asm("tanh.approx.f16x2 %0, %1;" : "=r"(y) : "r"(x));
    return y;
}

// ------------------------------------------------------------------
// lengths (ids are int32)
// ------------------------------------------------------------------
__global__ void k_lens(const int* __restrict__ ids, const int* __restrict__ tids) {
    int b = blockIdx.x;
    __shared__ int sm[128];
    int tid = threadIdx.x;
    int c = 0;
    for (int s = tid; s < NS; s += 128) c += (ids[b * NS + s] != 0);
    sm[tid] = c;
    __syncthreads();
    for (int o = 64; o > 0; o >>= 1) {
        if (tid < o) sm[tid] += sm[tid + o];
        __syncthreads();
    }
    if (tid == 0) {
        g_mlen[b] = fmaxf((float)sm[0], 1.0f);
        int a = 0;
        for (int t = 0; t < NTA; t++) a += (tids[b * NTA + t] != 0);
        g_alen[b] = fmaxf((float)a, 1.0f);
    }
}

// ------------------------------------------------------------------
// split memory -> bf16 hi/lo
// ------------------------------------------------------------------
__global__ __launch_bounds__(256) void k_prep_a(const float* __restrict__ mem) {
    size_t i = ((size_t)blockIdx.x * 256 + threadIdx.x) * 4;
    float4 v = *(const float4*)(mem + i);
    float vv[4] = {v.x, v.y, v.z, v.w};
    __nv_bfloat16 h[4], l[4];
#pragma unroll
    for (int j = 0; j < 4; j++) {
        h[j] = __float2bfloat16(vv[j]);
        l[j] = __float2bfloat16(vv[j] - __bfloat162float(h[j]));
    }
    *(uint2*)(g_Ahi + i) = *(uint2*)h;
    *(uint2*)(g_Alo + i) = *(uint2*)l;
}

// transpose + split W1_m: g_B[n][k] = W1[k][n]
__global__ void k_prep_b(const float* __restrict__ W1) {
    __shared__ float t[32][33];
    int k0 = blockIdx.x * 32, n0 = blockIdx.y * 32;
    int tx = threadIdx.x, ty = threadIdx.y;
    for (int i = ty; i < 32; i += 8)
        t[i][tx] = W1[(size_t)(k0 + i) * ND + n0 + tx];
    __syncthreads();
    for (int i = ty; i < 32; i += 8) {
        float v = t[tx][i];
        __nv_bfloat16 h = __float2bfloat16(v);
        __nv_bfloat16 l = __float2bfloat16(v - __bfloat162float(h));
        g_Bhi[(size_t)(n0 + i) * ND + k0 + tx] = h;
        g_Blo[(size_t)(n0 + i) * ND + k0 + tx] = l;
    }
}

// ------------------------------------------------------------------
// means: v_s, v_a  (512 threads: 4-way s-split)
// ------------------------------------------------------------------
__global__ __launch_bounds__(512) void k_means(const float* __restrict__ mem,
                                               const float* __restrict__ asp) {
    __shared__ float sp[4][128];
    int b = blockIdx.y;
    int tid = threadIdx.x;
    int d = blockIdx.x * 128 + (tid & 127);
    int q = tid >> 7;
    float acc = 0.f;
    const float* p = mem + ((size_t)b * NS + q * 128) * ND + d;
#pragma unroll 8
    for (int s = 0; s < 128; s++) acc += p[(size_t)s * ND];
    sp[q][tid & 127] = acc;
    __syncthreads();
    if (q == 0) {
        float tot = sp[0][tid] + sp[1][tid] + sp[2][tid] + sp[3][tid];
        g_vs[b * ND + d] = tot / g_mlen[b];
        float a = 0.f;
        const float* ap = asp + ((size_t)b * NTA) * ND + d;
#pragma unroll
        for (int t = 0; t < NTA; t++) a += ap[(size_t)t * ND];
        g_va[b * ND + d] = a / g_alen[b];
    }
}

// ------------------------------------------------------------------
// ctx = v_a @ W1_a + v_s @ W1_s + b1  (512 threads: 4-way split)
// ------------------------------------------------------------------
__global__ __launch_bounds__(512) void k_ctx(const float* __restrict__ W1,
                                             const float* __restrict__ b1) {
    __shared__ float sp[4][128];
    int b = blockIdx.y;
    int tid = threadIdx.x;
    int d = blockIdx.x * 128 + (tid & 127);
    int q = tid >> 7;                     // 0,1 -> Wa halves; 2,3 -> Ws halves
    const float* W = W1 + (size_t)(1 + (q >> 1)) * ND * ND + d;
    const float* vv = ((q >> 1) ? g_vs : g_va) + b * ND;
    int k0 = (q & 1) * 384;
    float acc = 0.f;
#pragma unroll 8
    for (int k = 0; k < 384; k++)
        acc = fmaf(vv[k0 + k], W[(size_t)(k0 + k) * ND], acc);
    sp[q][tid & 127] = acc;
    __syncthreads();
    if (q == 0)
        g_ctx[b * ND + d] = sp[0][tid] + sp[1][tid] + sp[2][tid] + sp[3][tid] + b1[d];
}

// ------------------------------------------------------------------
// fused scores: mma.sync bf16 3xMMA GEMM + tanh/w2 epilogue
//   CTA: M=128 rows, N=128 chunk (6 chunks), K=768
// ------------------------------------------------------------------
#define MT 128
#define NTILE 128
#define KC 32
#define NCHUNKS (ND / NTILE)   // 6
#define KSTEPS (ND / KC)       // 24
#define APAD 80                // padded row stride (bytes): conflict-free ldmatrix

#define OFF_AH 0
#define OFF_AL 10240
#define OFF_BH 20480
#define OFF_BL 30720
#define BUFSZ  40960
#define OFF_CTX (2 * BUFSZ)          // 81920
#define OFF_W2  (OFF_CTX + 3072)     // 84992
#define OFF_RED (OFF_W2 + 3072)      // 88064
#define SMEMSZ  (OFF_RED + 1024)     // 89088

struct ScoreCtx {
    const __nv_bfloat16* gAh;
    const __nv_bfloat16* gAl;
    uint32_t sbase;
};

__device__ __forceinline__ void stage_tiles(const ScoreCtx& sc, int nbase, int k0, int buf) {
    int tid = threadIdx.x;
    uint32_t sb = sc.sbase + buf * BUFSZ;
#pragma unroll
    for (int t = 0; t < 2; t++) {
        int i = tid + t * 256;
        int r = i >> 2, c = i & 3;          // r: 0..127, c: 0..3 (16B each, 64B row)
        uint32_t d = sb + r * APAD + c * 16;
        cp16(d + OFF_AH, sc.gAh + (size_t)r * ND + k0 + c * 8);
        cp16(d + OFF_AL, sc.gAl + (size_t)r * ND + k0 + c * 8);
        cp16(d + OFF_BH, g_Bhi + (size_t)(nbase + r) * ND + k0 + c * 8);
        cp16(d + OFF_BL, g_Blo + (size_t)(nbase + r) * ND + k0 + c * 8);
    }
}

__global__ void __launch_bounds__(256, 2) k_scores(const float* __restrict__ w2) {
    extern __shared__ char smem[];
    const int tid = threadIdx.x;
    const int b = blockIdx.y;
    const int s0 = blockIdx.x * MT;
    const int lane = tid & 31, wid = tid >> 5;
    const int warp_m = wid & 3, warp_n = wid >> 2;   // 4 m-warps x 2 n-warps

    float* sctx = (float*)(smem + OFF_CTX);
    float* sw2p = (float*)(smem + OFF_W2);
    for (int i = tid; i < ND; i += 256) {
        sctx[i] = g_ctx[b * ND + i];
        sw2p[i] = w2[i];
    }

    ScoreCtx sc;
    sc.gAh = g_Ahi + ((size_t)b * NS + s0) * ND;
    sc.gAl = g_Alo + ((size_t)b * NS + s0) * ND;
    sc.sbase = smem_u32(smem);

    const float mlen = g_mlen[b];
    float loc[2][2], rowsum[2][2];
#pragma unroll
    for (int mt = 0; mt < 2; mt++)
#pragma unroll
        for (int h = 0; h < 2; h++) {
            float srow = (float)(s0 + warp_m * 32 + mt * 16 + h * 8 + (lane >> 2));
            loc[mt][h] = (srow < mlen) ? (1.0f - srow / mlen) : 1.0f;
            rowsum[mt][h] = 0.f;
        }

    // ldmatrix lane geometry
    const int a_row = warp_m * 32 + (lane & 7) + ((lane >> 3) & 1) * 8;  // + mt*16
    const int a_halfoff = (lane >> 4) * 16;
    const int b_row = warp_n * 64 + (lane & 7) + (lane >> 4) * 8;        // + nt2*16
    const int b_halfoff = ((lane >> 3) & 1) * 16;

    __syncthreads();  // sctx/sw2 ready

    // prologue: stage chunk0 / ks0 into buf0
    stage_tiles(sc, 0, 0, 0);
    CP_COMMIT();

    for (int chunk = 0; chunk < NCHUNKS; chunk++) {
        const int nbase = chunk * NTILE;
        float acc[2][8][4];
#pragma unroll
        for (int mt = 0; mt < 2; mt++)
#pragma unroll
            for (int nt = 0; nt < 8; nt++)
#pragma unroll
                for (int j = 0; j < 4; j++) acc[mt][nt][j] = 0.f;

        for (int ks = 0; ks < KSTEPS; ks++) {
            const int buf = ks & 1;
            if (ks + 1 < KSTEPS) {
                stage_tiles(sc, nbase, (ks + 1) * KC, buf ^ 1);
                CP_COMMIT();
                CP_WAIT1();
            } else {
                CP_WAIT0();
            }
            __syncthreads();

            const uint32_t sb = sc.sbase + buf * BUFSZ;
#pragma unroll
            for (int kk = 0; kk < 2; kk++) {
                const int kb = kk * 32;
                uint32_t ah[2][4], bh[4][4];
#pragma unroll
                for (int mt = 0; mt < 2; mt++)
                    ldsm4(ah[mt][0], ah[mt][1], ah[mt][2], ah[mt][3],
                          sb + OFF_AH + (a_row + mt * 16) * APAD + kb + a_halfoff);
#pragma unroll
                for (int nt2 = 0; nt2 < 4; nt2++)
                    ldsm4(bh[nt2][0], bh[nt2][1], bh[nt2][2], bh[nt2][3],
                          sb + OFF_BH + (b_row + nt2 * 16) * APAD + kb + b_halfoff);
                // Ah * Bh
#pragma unroll
                for (int mt = 0; mt < 2; mt++)
#pragma unroll
                    for (int nt2 = 0; nt2 < 4; nt2++)
#pragma unroll
                        for (int s = 0; s < 2; s++)
                            mma16816(acc[mt][nt2 * 2 + s], ah[mt][0], ah[mt][1], ah[mt][2],
                                     ah[mt][3], bh[nt2][2 * s], bh[nt2][2 * s + 1]);
                // Al * Bh (Bh reused; Ah stays live)
                {
                    uint32_t al[2][4];
#pragma unroll
                    for (int mt = 0; mt < 2; mt++)
                        ldsm4(al[mt][0], al[mt][1], al[mt][2], al[mt][3],
                              sb + OFF_AL + (a_row + mt * 16) * APAD + kb + a_halfoff);
#pragma unroll
                    for (int mt = 0; mt < 2; mt++)
#pragma unroll
                        for (int nt2 = 0; nt2 < 4; nt2++)
#pragma unroll
                            for (int s = 0; s < 2; s++)
                                mma16816(acc[mt][nt2 * 2 + s], al[mt][0], al[mt][1], al[mt][2],
                                         al[mt][3], bh[nt2][2 * s], bh[nt2][2 * s + 1]);
                }
                // Ah * Bl (Ah reused)
                {
                    uint32_t bl[4][4];
#pragma unroll
                    for (int nt2 = 0; nt2 < 4; nt2++)
                        ldsm4(bl[nt2][0], bl[nt2][1], bl[nt2][2], bl[nt2][3],
                              sb + OFF_BL + (b_row + nt2 * 16) * APAD + kb + b_halfoff);
#pragma unroll
                    for (int mt = 0; mt < 2; mt++)
#pragma unroll
                        for (int nt2 = 0; nt2 < 4; nt2++)
#pragma unroll
                            for (int s = 0; s < 2; s++)
                                mma16816(acc[mt][nt2 * 2 + s], ah[mt][0], ah[mt][1], ah[mt][2],
                                         ah[mt][3], bl[nt2][2 * s], bl[nt2][2 * s + 1]);
                }
            }
            __syncthreads();
        }

        // prefetch next chunk's first stage (overlaps with epilogue MUFU work)
        if (chunk + 1 < NCHUNKS) {
            stage_tiles(sc, nbase + NTILE, 0, 0);
            CP_COMMIT();
        }

        // epilogue: tanh (f16x2) + dot with w2
#pragma unroll
        for (int mt = 0; mt < 2; mt++) {
#pragma unroll
            for (int nt = 0; nt < 8; nt++) {
                const int c0 = nbase + warp_n * 64 + nt * 8 + (lane & 3) * 2;
                const float2 cx = *(const float2*)&sctx[c0];
                const float2 wv = *(const float2*)&sw2p[c0];
                {
                    float u0 = fmaf(loc[mt][0], acc[mt][nt][0], cx.x);
                    float u1 = fmaf(loc[mt][0], acc[mt][nt][1], cx.y);
                    __half2 hp = __floats2half2_rn(u0, u1);
                    uint32_t th = tanh2_f16(*(uint32_t*)&hp);
                    float2 tf = __half22float2(*(__half2*)&th);
                    rowsum[mt][0] = fmaf(tf.x, wv.x, fmaf(tf.y, wv.y, rowsum[mt][0]));
                }
                {
                    float u2 = fmaf(loc[mt][1], acc[mt][nt][2], cx.x);
                    float u3 = fmaf(loc[mt][1], acc[mt][nt][3], cx.y);
                    __half2 hp = __floats2half2_rn(u2, u3);
                    uint32_t th = tanh2_f16(*(uint32_t*)&hp);
                    float2 tf = __half22float2(*(__half2*)&th);
                    rowsum[mt][1] = fmaf(tf.x, wv.x, fmaf(tf.y, wv.y, rowsum[mt][1]));
                }
            }
        }
    }

    // reduce across the 4 lanes of each quad, then across warp_n via smem
    float* red = (float*)(smem + OFF_RED);
#pragma unroll
    for (int mt = 0; mt < 2; mt++)
#pragma unroll
        for (int h = 0; h < 2; h++) {
            float v = rowsum[mt][h];
            v += __shfl_xor_sync(0xffffffffu, v, 1);
            v += __shfl_xor_sync(0xffffffffu, v, 2);
            if ((lane & 3) == 0) {
                int lrow = warp_m * 32 + mt * 16 + h * 8 + (lane >> 2);
                red[lrow * 2 + warp_n] = v;
            }
        }
    __syncthreads();
    if (tid < MT)
        g_scores[b * NS + s0 + tid] = red[tid * 2] + red[tid * 2 + 1];
}

// ------------------------------------------------------------------
// softmax + v_ts + v_ns  (512 threads)
// ------------------------------------------------------------------
__global__ __launch_bounds__(512) void k_soft_vts(const float* __restrict__ mem) {
    int b = blockIdx.x;
    int tid = threadIdx.x;
    __shared__ float sw[NS];
    __shared__ float red[512];
    __shared__ float sp[2][256];
    float mlen = g_mlen[b];

    float v = g_scores[b * NS + tid];
    red[tid] = v;
    __syncthreads();
    for (int o = 256; o > 0; o >>= 1) {
        if (tid < o) red[tid] = fmaxf(red[tid], red[tid + o]);
        __syncthreads();
    }
    float m = red[0];
    __syncthreads();
    float e = expf(v - m);
    red[tid] = e;
    __syncthreads();
    for (int o = 256; o > 0; o >>= 1) {
        if (tid < o) red[tid] += red[tid + o];
        __syncthreads();
    }
    float inv = 1.0f / red[0];
    __syncthreads();
    float s = (float)tid;
    float l = (s < mlen) ? (1.0f - s / mlen) : 1.0f;
    sw[tid] = e * inv * l;
    __syncthreads();

    int dq = tid >> 8;
    int dd = tid & 255;
    for (int dc = 0; dc < 3; dc++) {
        int d = dc * 256 + dd;
        const float* p = mem + ((size_t)b * NS + dq * 256) * ND + d;
        float acc = 0.f;
#pragma unroll 8
        for (int s2 = 0; s2 < 256; s2++)
            acc = fmaf(sw[dq * 256 + s2], p[(size_t)s2 * ND], acc);
        sp[dq][dd] = acc;
        __syncthreads();
        if (dq == 0)
            g_vns[b * ND + d] = sp[0][dd] + sp[1][dd] + g_vs[b * ND + d];
        __syncthreads();
    }
}

// ------------------------------------------------------------------
// v_ms = tanh(v_ns @ Wm + bm)  (512 threads: 4-way k-split)
// ------------------------------------------------------------------
__global__ __launch_bounds__(512) void k_vms(const float* __restrict__ Wm,
                                             const float* __restrict__ bm) {
    __shared__ float sp[4][128];
    int b = blockIdx.y;
    int tid = threadIdx.x;
    int d = blockIdx.x * 128 + (tid & 127);
    int q = tid >> 7;
    const float* vv = g_vns + b * ND;
    int k0 = q * 192;
    float acc = 0.f;
#pragma unroll 8
    for (int k = 0; k < 192; k++)
        acc = fmaf(vv[k0 + k], Wm[(size_t)(k0 + k) * ND + d], acc);
    sp[q][tid & 127] = acc;
    __syncthreads();
    if (q == 0)
        g_vms[b * ND + d] = tanhf(sp[0][tid] + sp[1][tid] + sp[2][tid] + sp[3][tid] + bm[d]);
}

// ------------------------------------------------------------------
// logits
// ------------------------------------------------------------------
__global__ void k_logits(const float* __restrict__ Wd,
                         const float* __restrict__ bd,
                         float* __restrict__ out) {
    int t = threadIdx.x;
    if (t >= NB * 3) return;
    int b = t / 3, j = t % 3;
    float acc = bd[j];
    const float* v = g_vms + b * ND;
#pragma unroll 4
    for (int d = 0; d < ND; d++) acc = fmaf(v[d], Wd[d * 3 + j], acc);
    out[b * 3 + j] = acc;
}

// ------------------------------------------------------------------
// launch
// ------------------------------------------------------------------
extern "C" void kernel_launch(void* const* d_in, const int* in_sizes, int n_in,
                              void* d_out, int out_size) {
    (void)in_sizes; (void)n_in; (void)out_size;
    const float* mem  = (const float*)d_in[0];
    const float* asp  = (const float*)d_in[1];
    const int* ids    = (const int*)d_in[2];
    const int* tids   = (const int*)d_in[3];
    const float* W1 = (const float*)d_in[4];
    const float* b1 = (const float*)d_in[5];
    const float* w2 = (const float*)d_in[6];
    const float* Wm = (const float*)d_in[7];
    const float* bm = (const float*)d_in[8];
    const float* Wd = (const float*)d_in[9];
    const float* bd = (const float*)d_in[10];
    float* out = (float*)d_out;

    cudaFuncSetAttribute(k_scores, cudaFuncAttributeMaxDynamicSharedMemorySize, SMEMSZ);

    k_lens<<<NB, 128>>>(ids, tids);
    k_prep_a<<<(int)(((size_t)NB * NS * ND) / (256 * 4)), 256>>>(mem);
    k_prep_b<<<dim3(ND / 32, ND / 32), dim3(32, 8)>>>(W1);
    k_means<<<dim3(ND / 128, NB), 512>>>(mem, asp);
    k_ctx<<<dim3(ND / 128, NB), 512>>>(W1, b1);
    k_scores<<<dim3(NS / MT, NB), 256, SMEMSZ>>>(w2);
    k_soft_vts<<<NB, 512>>>(mem);
    k_vms<<<dim3(ND / 128, NB), 512>>>(Wm, bm);
    k_logits<<<1, 256>>>(Wd, bd, out);
}

// round 6
// speedup vs baseline: 4.7421x; 1.6419x over previous
#include <cuda_runtime.h>
#include <cuda_fp16.h>
#include <cstdint>

#define NB 64
#define NS 512
#define NTA 8
#define ND 768

// ------------------------------------------------------------------
// scratch (static __device__; no allocations allowed)
// ------------------------------------------------------------------
__device__ float g_mlen[NB], g_alen[NB];
__device__ float g_va[NB * ND], g_vs[NB * ND], g_ctx[NB * ND];
__device__ float g_scores[NB * NS];
__device__ float g_vns[NB * ND], g_vms[NB * ND];

// fp16 operands
__device__ __half g_Ah[(size_t)NB * NS * ND];
__device__ __half g_Bh[(size_t)ND * ND];   // [n][k] = W1_m[k][n]

// ------------------------------------------------------------------
// PTX helpers (baseline ISA only)
// ------------------------------------------------------------------
__device__ __forceinline__ uint32_t smem_u32(const void* p) {
    uint32_t a;
    asm("{ .reg .u64 t; cvta.to.shared.u64 t, %1; cvt.u32.u64 %0, t; }" : "=r"(a) : "l"(p));
    return a;
}
__device__ __forceinline__ void cp16(uint32_t dst, const void* src) {
    asm volatile("cp.async.cg.shared.global [%0], [%1], 16;" :: "r"(dst), "l"(src));
}
#define CP_COMMIT() asm volatile("cp.async.commit_group;" ::: "memory")
#define CP_WAIT1()  asm volatile("cp.async.wait_group 1;" ::: "memory")
#define CP_WAIT0()  asm volatile("cp.async.wait_group 0;" ::: "memory")

__device__ __forceinline__ void ldsm4(uint32_t& r0, uint32_t& r1, uint32_t& r2, uint32_t& r3,
                                      uint32_t addr) {
    asm volatile("ldmatrix.sync.aligned.m8n8.x4.shared.b16 {%0,%1,%2,%3}, [%4];"
                 : "=r"(r0), "=r"(r1), "=r"(r2), "=r"(r3) : "r"(addr));
}
__device__ __forceinline__ void mma16816(float* c, uint32_t a0, uint32_t a1, uint32_t a2,
                                         uint32_t a3, uint32_t b0, uint32_t b1) {
    asm volatile(
        "mma.sync.aligned.m16n8k16.row.col.f32.f16.f16.f32 "
        "{%0,%1,%2,%3}, {%4,%5,%6,%7}, {%8,%9}, {%0,%1,%2,%3};"
        : "+f"(c[0]), "+f"(c[1]), "+f"(c[2]), "+f"(c[3])
        : "r"(a0), "r"(a1), "r"(a2), "r"(a3), "r"(b0), "r"(b1));
}
__device__ __forceinline__ uint32_t tanh2_f16(uint32_t x) {
    uint32_t y;
    asm("tanh.approx.f16x2 %0, %1;" : "=r"(y) : "r"(x));
    return y;
}

// ------------------------------------------------------------------
// lengths (ids are int32)
// ------------------------------------------------------------------
__global__ void k_lens(const int* __restrict__ ids, const int* __restrict__ tids) {
    int b = blockIdx.x;
    __shared__ int sm[128];
    int tid = threadIdx.x;
    int c = 0;
    for (int s = tid; s < NS; s += 128) c += (ids[b * NS + s] != 0);
    sm[tid] = c;
    __syncthreads();
    for (int o = 64; o > 0; o >>= 1) {
        if (tid < o) sm[tid] += sm[tid + o];
        __syncthreads();
    }
    if (tid == 0) {
        g_mlen[b] = fmaxf((float)sm[0], 1.0f);
        int a = 0;
        for (int t = 0; t < NTA; t++) a += (tids[b * NTA + t] != 0);
        g_alen[b] = fmaxf((float)a, 1.0f);
    }
}

// ------------------------------------------------------------------
// convert memory -> fp16
// ------------------------------------------------------------------
__global__ __launch_bounds__(256) void k_prep_a(const float* __restrict__ mem) {
    size_t i = ((size_t)blockIdx.x * 256 + threadIdx.x) * 8;
    float4 v0 = *(const float4*)(mem + i);
    float4 v1 = *(const float4*)(mem + i + 4);
    __half h[8];
    h[0] = __float2half_rn(v0.x); h[1] = __float2half_rn(v0.y);
    h[2] = __float2half_rn(v0.z); h[3] = __float2half_rn(v0.w);
    h[4] = __float2half_rn(v1.x); h[5] = __float2half_rn(v1.y);
    h[6] = __float2half_rn(v1.z); h[7] = __float2half_rn(v1.w);
    *(uint4*)(g_Ah + i) = *(uint4*)h;
}

// transpose + convert W1_m: g_Bh[n][k] = W1[k][n]
__global__ void k_prep_b(const float* __restrict__ W1) {
    __shared__ float t[32][33];
    int k0 = blockIdx.x * 32, n0 = blockIdx.y * 32;
    int tx = threadIdx.x, ty = threadIdx.y;
    for (int i = ty; i < 32; i += 8)
        t[i][tx] = W1[(size_t)(k0 + i) * ND + n0 + tx];
    __syncthreads();
    for (int i = ty; i < 32; i += 8)
        g_Bh[(size_t)(n0 + i) * ND + k0 + tx] = __float2half_rn(t[tx][i]);
}

// ------------------------------------------------------------------
// means: v_s, v_a  (512 threads: 4-way s-split)
// ------------------------------------------------------------------
__global__ __launch_bounds__(512) void k_means(const float* __restrict__ mem,
                                               const float* __restrict__ asp) {
    __shared__ float sp[4][128];
    int b = blockIdx.y;
    int tid = threadIdx.x;
    int d = blockIdx.x * 128 + (tid & 127);
    int q = tid >> 7;
    float acc = 0.f;
    const float* p = mem + ((size_t)b * NS + q * 128) * ND + d;
#pragma unroll 8
    for (int s = 0; s < 128; s++) acc += p[(size_t)s * ND];
    sp[q][tid & 127] = acc;
    __syncthreads();
    if (q == 0) {
        float tot = sp[0][tid] + sp[1][tid] + sp[2][tid] + sp[3][tid];
        g_vs[b * ND + d] = tot / g_mlen[b];
        float a = 0.f;
        const float* ap = asp + ((size_t)b * NTA) * ND + d;
#pragma unroll
        for (int t = 0; t < NTA; t++) a += ap[(size_t)t * ND];
        g_va[b * ND + d] = a / g_alen[b];
    }
}

// ------------------------------------------------------------------
// ctx = v_a @ W1_a + v_s @ W1_s + b1  (512 threads: 4-way split)
// ------------------------------------------------------------------
__global__ __launch_bounds__(512) void k_ctx(const float* __restrict__ W1,
                                             const float* __restrict__ b1) {
    __shared__ float sp[4][128];
    int b = blockIdx.y;
    int tid = threadIdx.x;
    int d = blockIdx.x * 128 + (tid & 127);
    int q = tid >> 7;                     // 0,1 -> Wa halves; 2,3 -> Ws halves
    const float* W = W1 + (size_t)(1 + (q >> 1)) * ND * ND + d;
    const float* vv = ((q >> 1) ? g_vs : g_va) + b * ND;
    int k0 = (q & 1) * 384;
    float acc = 0.f;
#pragma unroll 8
    for (int k = 0; k < 384; k++)
        acc = fmaf(vv[k0 + k], W[(size_t)(k0 + k) * ND], acc);
    sp[q][tid & 127] = acc;
    __syncthreads();
    if (q == 0)
        g_ctx[b * ND + d] = sp[0][tid] + sp[1][tid] + sp[2][tid] + sp[3][tid] + b1[d];
}

// ------------------------------------------------------------------
// fused scores: mma.sync fp16 single-pass GEMM + tanh/w2 epilogue
//   CTA: M=128 rows, N=128 chunk (6 chunks), K=768
// ------------------------------------------------------------------
#define MT 128
#define NTILE 128
#define KC 32
#define NCHUNKS (ND / NTILE)   // 6
#define KSTEPS (ND / KC)       // 24
#define APAD 80                // padded row stride (bytes): conflict-free ldmatrix

#define OFF_A 0
#define OFF_B 10240
#define BUFSZ 20480
#define OFF_CTX (2 * BUFSZ)          // 40960
#define OFF_W2  (OFF_CTX + 3072)     // 44032
#define OFF_RED (OFF_W2 + 3072)      // 47104
#define SMEMSZ  (OFF_RED + 1024)     // 48128

struct ScoreCtx {
    const __half* gA;
    uint32_t sbase;
};

__device__ __forceinline__ void stage_tiles(const ScoreCtx& sc, int nbase, int k0, int buf) {
    int tid = threadIdx.x;
    uint32_t sb = sc.sbase + buf * BUFSZ;
#pragma unroll
    for (int t = 0; t < 2; t++) {
        int i = tid + t * 256;
        int r = i >> 2, c = i & 3;          // r: 0..127, c: 0..3 (16B each, 64B row)
        uint32_t d = sb + r * APAD + c * 16;
        cp16(d + OFF_A, sc.gA + (size_t)r * ND + k0 + c * 8);
        cp16(d + OFF_B, g_Bh + (size_t)(nbase + r) * ND + k0 + c * 8);
    }
}

__global__ void __launch_bounds__(256, 2) k_scores(const float* __restrict__ w2) {
    extern __shared__ char smem[];
    const int tid = threadIdx.x;
    const int b = blockIdx.y;
    const int s0 = blockIdx.x * MT;
    const int lane = tid & 31, wid = tid >> 5;
    const int warp_m = wid & 3, warp_n = wid >> 2;   // 4 m-warps x 2 n-warps

    float* sctx = (float*)(smem + OFF_CTX);
    float* sw2p = (float*)(smem + OFF_W2);
    for (int i = tid; i < ND; i += 256) {
        sctx[i] = g_ctx[b * ND + i];
        sw2p[i] = w2[i];
    }

    ScoreCtx sc;
    sc.gA = g_Ah + ((size_t)b * NS + s0) * ND;
    sc.sbase = smem_u32(smem);

    const float mlen = g_mlen[b];
    float loc[2][2], rowsum[2][2];
#pragma unroll
    for (int mt = 0; mt < 2; mt++)
#pragma unroll
        for (int h = 0; h < 2; h++) {
            float srow = (float)(s0 + warp_m * 32 + mt * 16 + h * 8 + (lane >> 2));
            loc[mt][h] = (srow < mlen) ? (1.0f - srow / mlen) : 1.0f;
            rowsum[mt][h] = 0.f;
        }

    // ldmatrix lane geometry
    const int a_row = warp_m * 32 + (lane & 7) + ((lane >> 3) & 1) * 8;  // + mt*16
    const int a_halfoff = (lane >> 4) * 16;
    const int b_row = warp_n * 64 + (lane & 7) + (lane >> 4) * 8;        // + nt2*16
    const int b_halfoff = ((lane >> 3) & 1) * 16;

    __syncthreads();  // sctx/sw2 ready

    // prologue: stage chunk0 / ks0 into buf0
    stage_tiles(sc, 0, 0, 0);
    CP_COMMIT();

    for (int chunk = 0; chunk < NCHUNKS; chunk++) {
        const int nbase = chunk * NTILE;
        float acc[2][8][4];
#pragma unroll
        for (int mt = 0; mt < 2; mt++)
#pragma unroll
            for (int nt = 0; nt < 8; nt++)
#pragma unroll
                for (int j = 0; j < 4; j++) acc[mt][nt][j] = 0.f;

        for (int ks = 0; ks < KSTEPS; ks++) {
            const int buf = ks & 1;
            if (ks + 1 < KSTEPS) {
                stage_tiles(sc, nbase, (ks + 1) * KC, buf ^ 1);
                CP_COMMIT();
                CP_WAIT1();
            } else {
                CP_WAIT0();
            }
            __syncthreads();

            const uint32_t sb = sc.sbase + buf * BUFSZ;
#pragma unroll
            for (int kk = 0; kk < 2; kk++) {
                const int kb = kk * 32;
                uint32_t ar[2][4], br[4][4];
#pragma unroll
                for (int mt = 0; mt < 2; mt++)
                    ldsm4(ar[mt][0], ar[mt][1], ar[mt][2], ar[mt][3],
                          sb + OFF_A + (a_row + mt * 16) * APAD + kb + a_halfoff);
#pragma unroll
                for (int nt2 = 0; nt2 < 4; nt2++)
                    ldsm4(br[nt2][0], br[nt2][1], br[nt2][2], br[nt2][3],
                          sb + OFF_B + (b_row + nt2 * 16) * APAD + kb + b_halfoff);
#pragma unroll
                for (int mt = 0; mt < 2; mt++)
#pragma unroll
                    for (int nt2 = 0; nt2 < 4; nt2++)
#pragma unroll
                        for (int s = 0; s < 2; s++)
                            mma16816(acc[mt][nt2 * 2 + s], ar[mt][0], ar[mt][1], ar[mt][2],
                                     ar[mt][3], br[nt2][2 * s], br[nt2][2 * s + 1]);
            }
            __syncthreads();
        }

        // prefetch next chunk's first stage (overlaps with epilogue MUFU work)
        if (chunk + 1 < NCHUNKS) {
            stage_tiles(sc, nbase + NTILE, 0, 0);
            CP_COMMIT();
        }

        // epilogue: tanh (f16x2) + dot with w2
#pragma unroll
        for (int mt = 0; mt < 2; mt++) {
#pragma unroll
            for (int nt = 0; nt < 8; nt++) {
                const int c0 = nbase + warp_n * 64 + nt * 8 + (lane & 3) * 2;
                const float2 cx = *(const float2*)&sctx[c0];
                const float2 wv = *(const float2*)&sw2p[c0];
                {
                    float u0 = fmaf(loc[mt][0], acc[mt][nt][0], cx.x);
                    float u1 = fmaf(loc[mt][0], acc[mt][nt][1], cx.y);
                    __half2 hp = __floats2half2_rn(u0, u1);
                    uint32_t th = tanh2_f16(*(uint32_t*)&hp);
                    float2 tf = __half22float2(*(__half2*)&th);
                    rowsum[mt][0] = fmaf(tf.x, wv.x, fmaf(tf.y, wv.y, rowsum[mt][0]));
                }
                {
                    float u2 = fmaf(loc[mt][1], acc[mt][nt][2], cx.x);
                    float u3 = fmaf(loc[mt][1], acc[mt][nt][3], cx.y);
                    __half2 hp = __floats2half2_rn(u2, u3);
                    uint32_t th = tanh2_f16(*(uint32_t*)&hp);
                    float2 tf = __half22float2(*(__half2*)&th);
                    rowsum[mt][1] = fmaf(tf.x, wv.x, fmaf(tf.y, wv.y, rowsum[mt][1]));
                }
            }
        }
    }

    // reduce across the 4 lanes of each quad, then across warp_n via smem
    float* red = (float*)(smem + OFF_RED);
#pragma unroll
    for (int mt = 0; mt < 2; mt++)
#pragma unroll
        for (int h = 0; h < 2; h++) {
            float v = rowsum[mt][h];
            v += __shfl_xor_sync(0xffffffffu, v, 1);
            v += __shfl_xor_sync(0xffffffffu, v, 2);
            if ((lane & 3) == 0) {
                int lrow = warp_m * 32 + mt * 16 + h * 8 + (lane >> 2);
                red[lrow * 2 + warp_n] = v;
            }
        }
    __syncthreads();
    if (tid < MT)
        g_scores[b * NS + s0 + tid] = red[tid * 2] + red[tid * 2 + 1];
}

// ------------------------------------------------------------------
// softmax + v_ts + v_ns  (512 threads)
// ------------------------------------------------------------------
__global__ __launch_bounds__(512) void k_soft_vts(const float* __restrict__ mem) {
    int b = blockIdx.x;
    int tid = threadIdx.x;
    __shared__ float sw[NS];
    __shared__ float red[512];
    __shared__ float sp[2][256];
    float mlen = g_mlen[b];

    float v = g_scores[b * NS + tid];
    red[tid] = v;
    __syncthreads();
    for (int o = 256; o > 0; o >>= 1) {
        if (tid < o) red[tid] = fmaxf(red[tid], red[tid + o]);
        __syncthreads();
    }
    float m = red[0];
    __syncthreads();
    float e = expf(v - m);
    red[tid] = e;
    __syncthreads();
    for (int o = 256; o > 0; o >>= 1) {
        if (tid < o) red[tid] += red[tid + o];
        __syncthreads();
    }
    float inv = 1.0f / red[0];
    __syncthreads();
    float s = (float)tid;
    float l = (s < mlen) ? (1.0f - s / mlen) : 1.0f;
    sw[tid] = e * inv * l;
    __syncthreads();

    int dq = tid >> 8;
    int dd = tid & 255;
    for (int dc = 0; dc < 3; dc++) {
        int d = dc * 256 + dd;
        const float* p = mem + ((size_t)b * NS + dq * 256) * ND + d;
        float acc = 0.f;
#pragma unroll 8
        for (int s2 = 0; s2 < 256; s2++)
            acc = fmaf(sw[dq * 256 + s2], p[(size_t)s2 * ND], acc);
        sp[dq][dd] = acc;
        __syncthreads();
        if (dq == 0)
            g_vns[b * ND + d] = sp[0][dd] + sp[1][dd] + g_vs[b * ND + d];
        __syncthreads();
    }
}

// ------------------------------------------------------------------
// v_ms = tanh(v_ns @ Wm + bm)  (512 threads: 4-way k-split)
// ------------------------------------------------------------------
__global__ __launch_bounds__(512) void k_vms(const float* __restrict__ Wm,
                                             const float* __restrict__ bm) {
    __shared__ float sp[4][128];
    int b = blockIdx.y;
    int tid = threadIdx.x;
    int d = blockIdx.x * 128 + (tid & 127);
    int q = tid >> 7;
    const float* vv = g_vns + b * ND;
    int k0 = q * 192;
    float acc = 0.f;
#pragma unroll 8
    for (int k = 0; k < 192; k++)
        acc = fmaf(vv[k0 + k], Wm[(size_t)(k0 + k) * ND + d], acc);
    sp[q][tid & 127] = acc;
    __syncthreads();
    if (q == 0)
        g_vms[b * ND + d] = tanhf(sp[0][tid] + sp[1][tid] + sp[2][tid] + sp[3][tid] + bm[d]);
}

// ------------------------------------------------------------------
// logits
// ------------------------------------------------------------------
__global__ void k_logits(const float* __restrict__ Wd,
                         const float* __restrict__ bd,
                         float* __restrict__ out) {
    int t = threadIdx.x;
    if (t >= NB * 3) return;
    int b = t / 3, j = t % 3;
    float acc = bd[j];
    const float* v = g_vms + b * ND;
#pragma unroll 4
    for (int d = 0; d < ND; d++) acc = fmaf(v[d], Wd[d * 3 + j], acc);
    out[b * 3 + j] = acc;
}

// ------------------------------------------------------------------
// launch
// ------------------------------------------------------------------
extern "C" void kernel_launch(void* const* d_in, const int* in_sizes, int n_in,
                              void* d_out, int out_size) {
    (void)in_sizes; (void)n_in; (void)out_size;
    const float* mem  = (const float*)d_in[0];
    const float* asp  = (const float*)d_in[1];
    const int* ids    = (const int*)d_in[2];
    const int* tids   = (const int*)d_in[3];
    const float* W1 = (const float*)d_in[4];
    const float* b1 = (const float*)d_in[5];
    const float* w2 = (const float*)d_in[6];
    const float* Wm = (const float*)d_in[7];
    const float* bm = (const float*)d_in[8];
    const float* Wd = (const float*)d_in[9];
    const float* bd = (const float*)d_in[10];
    float* out = (float*)d_out;

    cudaFuncSetAttribute(k_scores, cudaFuncAttributeMaxDynamicSharedMemorySize, SMEMSZ);

    k_lens<<<NB, 128>>>(ids, tids);
    k_prep_a<<<(int)(((size_t)NB * NS * ND) / (256 * 8)), 256>>>(mem);
    k_prep_b<<<dim3(ND / 32, ND / 32), dim3(32, 8)>>>(W1);
    k_means<<<dim3(ND / 128, NB), 512>>>(mem, asp);
    k_ctx<<<dim3(ND / 128, NB), 512>>>(W1, b1);
    k_scores<<<dim3(NS / MT, NB), 256, SMEMSZ>>>(w2);
    k_soft_vts<<<NB, 512>>>(mem);
    k_vms<<<dim3(ND / 128, NB), 512>>>(Wm, bm);
    k_logits<<<1, 256>>>(Wd, bd, out);
}

// round 7
// speedup vs baseline: 5.3673x; 1.1318x over previous
#include <cuda_runtime.h>
#include <cuda_fp16.h>
#include <cstdint>

#define NB 64
#define NS 512
#define NTA 8
#define ND 768

// ------------------------------------------------------------------
// scratch (static __device__; no allocations allowed)
// ------------------------------------------------------------------
__device__ float g_mlen[NB], g_alen[NB];
__device__ float g_va[NB * ND], g_vs[NB * ND], g_ctx[NB * ND];
__device__ float g_scores[NB * NS];
__device__ float g_vns[NB * ND], g_vms[NB * ND];

// fp16 operands
__device__ __half g_Ah[(size_t)NB * NS * ND];
__device__ __half g_Bh[(size_t)ND * ND];   // [n][k] = W1_m[k][n]

// ------------------------------------------------------------------
// PTX helpers (baseline ISA only)
// ------------------------------------------------------------------
__device__ __forceinline__ uint32_t smem_u32(const void* p) {
    uint32_t a;
    asm("{ .reg .u64 t; cvta.to.shared.u64 t, %1; cvt.u32.u64 %0, t; }" : "=r"(a) : "l"(p));
    return a;
}
__device__ __forceinline__ void cp16(uint32_t dst, const void* src) {
    asm volatile("cp.async.cg.shared.global [%0], [%1], 16;" :: "r"(dst), "l"(src));
}
#define CP_COMMIT() asm volatile("cp.async.commit_group;" ::: "memory")
#define CP_WAIT1()  asm volatile("cp.async.wait_group 1;" ::: "memory")
#define CP_WAIT0()  asm volatile("cp.async.wait_group 0;" ::: "memory")

__device__ __forceinline__ void ldsm4(uint32_t& r0, uint32_t& r1, uint32_t& r2, uint32_t& r3,
                                      uint32_t addr) {
    asm volatile("ldmatrix.sync.aligned.m8n8.x4.shared.b16 {%0,%1,%2,%3}, [%4];"
                 : "=r"(r0), "=r"(r1), "=r"(r2), "=r"(r3) : "r"(addr));
}
__device__ __forceinline__ void mma16816(float* c, uint32_t a0, uint32_t a1, uint32_t a2,
                                         uint32_t a3, uint32_t b0, uint32_t b1) {
    asm volatile(
        "mma.sync.aligned.m16n8k16.row.col.f32.f16.f16.f32 "
        "{%0,%1,%2,%3}, {%4,%5,%6,%7}, {%8,%9}, {%0,%1,%2,%3};"
        : "+f"(c[0]), "+f"(c[1]), "+f"(c[2]), "+f"(c[3])
        : "r"(a0), "r"(a1), "r"(a2), "r"(a3), "r"(b0), "r"(b1));
}
__device__ __forceinline__ uint32_t tanh2_f16(uint32_t x) {
    uint32_t y;
    asm("tanh.approx.f16x2 %0, %1;" : "=r"(y) : "r"(x));
    return y;
}

// ------------------------------------------------------------------
// lengths (ids are int32)
// ------------------------------------------------------------------
__global__ void k_lens(const int* __restrict__ ids, const int* __restrict__ tids) {
    int b = blockIdx.x;
    __shared__ int sm[128];
    int tid = threadIdx.x;
    int c = 0;
    for (int s = tid; s < NS; s += 128) c += (ids[b * NS + s] != 0);
    sm[tid] = c;
    __syncthreads();
    for (int o = 64; o > 0; o >>= 1) {
        if (tid < o) sm[tid] += sm[tid + o];
        __syncthreads();
    }
    if (tid == 0) {
        g_mlen[b] = fmaxf((float)sm[0], 1.0f);
        int a = 0;
        for (int t = 0; t < NTA; t++) a += (tids[b * NTA + t] != 0);
        g_alen[b] = fmaxf((float)a, 1.0f);
    }
}

// transpose + convert W1_m: g_Bh[n][k] = W1[k][n]
__global__ void k_prep_b(const float* __restrict__ W1) {
    __shared__ float t[32][33];
    int k0 = blockIdx.x * 32, n0 = blockIdx.y * 32;
    int tx = threadIdx.x, ty = threadIdx.y;
    for (int i = ty; i < 32; i += 8)
        t[i][tx] = W1[(size_t)(k0 + i) * ND + n0 + tx];
    __syncthreads();
    for (int i = ty; i < 32; i += 8)
        g_Bh[(size_t)(n0 + i) * ND + k0 + tx] = __float2half_rn(t[tx][i]);
}

// ------------------------------------------------------------------
// means + fp16 convert of memory (single 100MB pass)
// ------------------------------------------------------------------
__global__ __launch_bounds__(512) void k_means(const float* __restrict__ mem,
                                               const float* __restrict__ asp) {
    __shared__ float sp[4][128];
    int b = blockIdx.y;
    int tid = threadIdx.x;
    int d = blockIdx.x * 128 + (tid & 127);
    int q = tid >> 7;
    float acc = 0.f;
    const float* p = mem + ((size_t)b * NS + q * 128) * ND + d;
    __half* ah = g_Ah + ((size_t)b * NS + q * 128) * ND + d;
#pragma unroll 8
    for (int s = 0; s < 128; s++) {
        float v = p[(size_t)s * ND];
        acc += v;
        ah[(size_t)s * ND] = __float2half_rn(v);
    }
    sp[q][tid & 127] = acc;
    __syncthreads();
    if (q == 0) {
        float tot = sp[0][tid] + sp[1][tid] + sp[2][tid] + sp[3][tid];
        g_vs[b * ND + d] = tot / g_mlen[b];
        float a = 0.f;
        const float* ap = asp + ((size_t)b * NTA) * ND + d;
#pragma unroll
        for (int t = 0; t < NTA; t++) a += ap[(size_t)t * ND];
        g_va[b * ND + d] = a / g_alen[b];
    }
}

// ------------------------------------------------------------------
// ctx = v_a @ W1_a + v_s @ W1_s + b1  (512 threads: 4-way split)
// ------------------------------------------------------------------
__global__ __launch_bounds__(512) void k_ctx(const float* __restrict__ W1,
                                             const float* __restrict__ b1) {
    __shared__ float sp[4][128];
    int b = blockIdx.y;
    int tid = threadIdx.x;
    int d = blockIdx.x * 128 + (tid & 127);
    int q = tid >> 7;                     // 0,1 -> Wa halves; 2,3 -> Ws halves
    const float* W = W1 + (size_t)(1 + (q >> 1)) * ND * ND + d;
    const float* vv = ((q >> 1) ? g_vs : g_va) + b * ND;
    int k0 = (q & 1) * 384;
    float acc = 0.f;
#pragma unroll 8
    for (int k = 0; k < 384; k++)
        acc = fmaf(vv[k0 + k], W[(size_t)(k0 + k) * ND], acc);
    sp[q][tid & 127] = acc;
    __syncthreads();
    if (q == 0)
        g_ctx[b * ND + d] = sp[0][tid] + sp[1][tid] + sp[2][tid] + sp[3][tid] + b1[d];
}

// ------------------------------------------------------------------
// fused scores: mma.sync fp16 GEMM + tanh/w2 epilogue
//   CTA: M=128 rows, N=128 chunk (6 chunks), K=768, KC=64
// ------------------------------------------------------------------
#define MT 128
#define NTILE 128
#define KC 64
#define NCHUNKS (ND / NTILE)   // 6
#define KSTEPS (ND / KC)       // 12
#define APAD 144               // 128B row + 16B pad: conflict-free ldmatrix

#define OFF_A 0
#define OFF_B 18432
#define BUFSZ 36864
#define OFF_CTX (2 * BUFSZ)          // 73728
#define OFF_W2  (OFF_CTX + 3072)     // 76800
#define OFF_RED (OFF_W2 + 3072)      // 79872
#define SMEMSZ  (OFF_RED + 1024)     // 80896

struct ScoreCtx {
    const __half* gA;
    uint32_t sbase;
};

__device__ __forceinline__ void stage_tiles(const ScoreCtx& sc, int nbase, int k0, int buf) {
    int tid = threadIdx.x;
    uint32_t sb = sc.sbase + buf * BUFSZ;
#pragma unroll
    for (int t = 0; t < 4; t++) {
        int i = tid + t * 256;
        int r = i >> 3, c = i & 7;          // r: 0..127, c: 0..7 (16B each, 128B row)
        uint32_t d = sb + r * APAD + c * 16;
        cp16(d + OFF_A, sc.gA + (size_t)r * ND + k0 + c * 8);
        cp16(d + OFF_B, g_Bh + (size_t)(nbase + r) * ND + k0 + c * 8);
    }
}

__global__ void __launch_bounds__(256, 2) k_scores(const float* __restrict__ w2) {
    extern __shared__ char smem[];
    const int tid = threadIdx.x;
    const int b = blockIdx.y;
    const int s0 = blockIdx.x * MT;
    const int lane = tid & 31, wid = tid >> 5;
    const int warp_m = wid & 3, warp_n = wid >> 2;   // 4 m-warps x 2 n-warps

    float* sctx = (float*)(smem + OFF_CTX);
    float* sw2p = (float*)(smem + OFF_W2);
    for (int i = tid; i < ND; i += 256) {
        sctx[i] = g_ctx[b * ND + i];
        sw2p[i] = w2[i];
    }

    ScoreCtx sc;
    sc.gA = g_Ah + ((size_t)b * NS + s0) * ND;
    sc.sbase = smem_u32(smem);

    const float mlen = g_mlen[b];
    float loc[2][2], rowsum[2][2];
#pragma unroll
    for (int mt = 0; mt < 2; mt++)
#pragma unroll
        for (int h = 0; h < 2; h++) {
            float srow = (float)(s0 + warp_m * 32 + mt * 16 + h * 8 + (lane >> 2));
            loc[mt][h] = (srow < mlen) ? (1.0f - srow / mlen) : 1.0f;
            rowsum[mt][h] = 0.f;
        }

    // ldmatrix lane geometry
    const int a_row = warp_m * 32 + (lane & 7) + ((lane >> 3) & 1) * 8;  // + mt*16
    const int a_halfoff = (lane >> 4) * 16;
    const int b_row = warp_n * 64 + (lane & 7) + (lane >> 4) * 8;        // + nt2*16
    const int b_halfoff = ((lane >> 3) & 1) * 16;

    __syncthreads();  // sctx/sw2 ready

    // prologue: stage chunk0 / ks0 into buf0
    stage_tiles(sc, 0, 0, 0);
    CP_COMMIT();

    for (int chunk = 0; chunk < NCHUNKS; chunk++) {
        const int nbase = chunk * NTILE;
        float acc[2][8][4];
#pragma unroll
        for (int mt = 0; mt < 2; mt++)
#pragma unroll
            for (int nt = 0; nt < 8; nt++)
#pragma unroll
                for (int j = 0; j < 4; j++) acc[mt][nt][j] = 0.f;

        for (int ks = 0; ks < KSTEPS; ks++) {
            const int buf = ks & 1;
            if (ks + 1 < KSTEPS) {
                stage_tiles(sc, nbase, (ks + 1) * KC, buf ^ 1);
                CP_COMMIT();
                CP_WAIT1();
            } else {
                CP_WAIT0();
            }
            __syncthreads();

            const uint32_t sb = sc.sbase + buf * BUFSZ;
#pragma unroll
            for (int kk = 0; kk < 4; kk++) {
                const int kb = kk * 32;
                uint32_t ar[2][4], br[4][4];
#pragma unroll
                for (int mt = 0; mt < 2; mt++)
                    ldsm4(ar[mt][0], ar[mt][1], ar[mt][2], ar[mt][3],
                          sb + OFF_A + (a_row + mt * 16) * APAD + kb + a_halfoff);
#pragma unroll
                for (int nt2 = 0; nt2 < 4; nt2++)
                    ldsm4(br[nt2][0], br[nt2][1], br[nt2][2], br[nt2][3],
                          sb + OFF_B + (b_row + nt2 * 16) * APAD + kb + b_halfoff);
#pragma unroll
                for (int mt = 0; mt < 2; mt++)
#pragma unroll
                    for (int nt2 = 0; nt2 < 4; nt2++)
#pragma unroll
                        for (int s = 0; s < 2; s++)
                            mma16816(acc[mt][nt2 * 2 + s], ar[mt][0], ar[mt][1], ar[mt][2],
                                     ar[mt][3], br[nt2][2 * s], br[nt2][2 * s + 1]);
            }
            __syncthreads();
        }

        // prefetch next chunk's first stage (overlaps with epilogue MUFU work)
        if (chunk + 1 < NCHUNKS) {
            stage_tiles(sc, nbase + NTILE, 0, 0);
            CP_COMMIT();
        }

        // epilogue: tanh (f16x2) + dot with w2
#pragma unroll
        for (int mt = 0; mt < 2; mt++) {
#pragma unroll
            for (int nt = 0; nt < 8; nt++) {
                const int c0 = nbase + warp_n * 64 + nt * 8 + (lane & 3) * 2;
                const float2 cx = *(const float2*)&sctx[c0];
                const float2 wv = *(const float2*)&sw2p[c0];
                {
                    float u0 = fmaf(loc[mt][0], acc[mt][nt][0], cx.x);
                    float u1 = fmaf(loc[mt][0], acc[mt][nt][1], cx.y);
                    __half2 hp = __floats2half2_rn(u0, u1);
                    uint32_t th = tanh2_f16(*(uint32_t*)&hp);
                    float2 tf = __half22float2(*(__half2*)&th);
                    rowsum[mt][0] = fmaf(tf.x, wv.x, fmaf(tf.y, wv.y, rowsum[mt][0]));
                }
                {
                    float u2 = fmaf(loc[mt][1], acc[mt][nt][2], cx.x);
                    float u3 = fmaf(loc[mt][1], acc[mt][nt][3], cx.y);
                    __half2 hp = __floats2half2_rn(u2, u3);
                    uint32_t th = tanh2_f16(*(uint32_t*)&hp);
                    float2 tf = __half22float2(*(__half2*)&th);
                    rowsum[mt][1] = fmaf(tf.x, wv.x, fmaf(tf.y, wv.y, rowsum[mt][1]));
                }
            }
        }
    }

    // reduce across the 4 lanes of each quad, then across warp_n via smem
    float* red = (float*)(smem + OFF_RED);
#pragma unroll
    for (int mt = 0; mt < 2; mt++)
#pragma unroll
        for (int h = 0; h < 2; h++) {
            float v = rowsum[mt][h];
            v += __shfl_xor_sync(0xffffffffu, v, 1);
            v += __shfl_xor_sync(0xffffffffu, v, 2);
            if ((lane & 3) == 0) {
                int lrow = warp_m * 32 + mt * 16 + h * 8 + (lane >> 2);
                red[lrow * 2 + warp_n] = v;
            }
        }
    __syncthreads();
    if (tid < MT)
        g_scores[b * NS + s0 + tid] = red[tid * 2] + red[tid * 2 + 1];
}

// ------------------------------------------------------------------
// softmax + v_ts + v_ns  (512 threads; reads fp16 memory copy)
// ------------------------------------------------------------------
__global__ __launch_bounds__(512) void k_soft_vts(const float* __restrict__ mem) {
    int b = blockIdx.x;
    int tid = threadIdx.x;
    __shared__ float sw[NS];
    __shared__ float red[512];
    __shared__ float sp[2][256];
    float mlen = g_mlen[b];

    float v = g_scores[b * NS + tid];
    red[tid] = v;
    __syncthreads();
    for (int o = 256; o > 0; o >>= 1) {
        if (tid < o) red[tid] = fmaxf(red[tid], red[tid + o]);
        __syncthreads();
    }
    float m = red[0];
    __syncthreads();
    float e = expf(v - m);
    red[tid] = e;
    __syncthreads();
    for (int o = 256; o > 0; o >>= 1) {
        if (tid < o) red[tid] += red[tid + o];
        __syncthreads();
    }
    float inv = 1.0f / red[0];
    __syncthreads();
    float s = (float)tid;
    float l = (s < mlen) ? (1.0f - s / mlen) : 1.0f;
    sw[tid] = e * inv * l;
    __syncthreads();

    int dq = tid >> 8;
    int dd = tid & 255;
    for (int dc = 0; dc < 3; dc++) {
        int d = dc * 256 + dd;
        const __half* p = g_Ah + ((size_t)b * NS + dq * 256) * ND + d;
        float acc = 0.f;
#pragma unroll 8
        for (int s2 = 0; s2 < 256; s2++)
            acc = fmaf(sw[dq * 256 + s2], __half2float(p[(size_t)s2 * ND]), acc);
        sp[dq][dd] = acc;
        __syncthreads();
        if (dq == 0)
            g_vns[b * ND + d] = sp[0][dd] + sp[1][dd] + g_vs[b * ND + d];
        __syncthreads();
    }
}

// ------------------------------------------------------------------
// v_ms = tanh(v_ns @ Wm + bm)  (512 threads: 4-way k-split)
// ------------------------------------------------------------------
__global__ __launch_bounds__(512) void k_vms(const float* __restrict__ Wm,
                                             const float* __restrict__ bm) {
    __shared__ float sp[4][128];
    int b = blockIdx.y;
    int tid = threadIdx.x;
    int d = blockIdx.x * 128 + (tid & 127);
    int q = tid >> 7;
    const float* vv = g_vns + b * ND;
    int k0 = q * 192;
    float acc = 0.f;
#pragma unroll 8
    for (int k = 0; k < 192; k++)
        acc = fmaf(vv[k0 + k], Wm[(size_t)(k0 + k) * ND + d], acc);
    sp[q][tid & 127] = acc;
    __syncthreads();
    if (q == 0)
        g_vms[b * ND + d] = tanhf(sp[0][tid] + sp[1][tid] + sp[2][tid] + sp[3][tid] + bm[d]);
}

// ------------------------------------------------------------------
// logits
// ------------------------------------------------------------------
__global__ void k_logits(const float* __restrict__ Wd,
                         const float* __restrict__ bd,
                         float* __restrict__ out) {
    int t = threadIdx.x;
    if (t >= NB * 3) return;
    int b = t / 3, j = t % 3;
    float acc = bd[j];
    const float* v = g_vms + b * ND;
#pragma unroll 4
    for (int d = 0; d < ND; d++) acc = fmaf(v[d], Wd[d * 3 + j], acc);
    out[b * 3 + j] = acc;
}

// ------------------------------------------------------------------
// launch
// ------------------------------------------------------------------
extern "C" void kernel_launch(void* const* d_in, const int* in_sizes, int n_in,
                              void* d_out, int out_size) {
    (void)in_sizes; (void)n_in; (void)out_size;
    const float* mem  = (const float*)d_in[0];
    const float* asp  = (const float*)d_in[1];
    const int* ids    = (const int*)d_in[2];
    const int* tids   = (const int*)d_in[3];
    const float* W1 = (const float*)d_in[4];
    const float* b1 = (const float*)d_in[5];
    const float* w2 = (const float*)d_in[6];
    const float* Wm = (const float*)d_in[7];
    const float* bm = (const float*)d_in[8];
    const float* Wd = (const float*)d_in[9];
    const float* bd = (const float*)d_in[10];
    float* out = (float*)d_out;

    cudaFuncSetAttribute(k_scores, cudaFuncAttributeMaxDynamicSharedMemorySize, SMEMSZ);

    k_lens<<<NB, 128>>>(ids, tids);
    k_prep_b<<<dim3(ND / 32, ND / 32), dim3(32, 8)>>>(W1);
    k_means<<<dim3(ND / 128, NB), 512>>>(mem, asp);
    k_ctx<<<dim3(ND / 128, NB), 512>>>(W1, b1);
    k_scores<<<dim3(NS / MT, NB), 256, SMEMSZ>>>(w2);
    k_soft_vts<<<NB, 512>>>(mem);
    k_vms<<<dim3(ND / 128, NB), 512>>>(Wm, bm);
    k_logits<<<1, 256>>>(Wd, bd, out);
}